// round 2
// baseline (speedup 1.0000x reference)
#include <cuda_runtime.h>
#include <cuda_bf16.h>

// Problem constants (fixed by the dataset)
#define N_TOTAL   10000
#define NUM_ATOMS 100
#define N_EDGES   1000000
#define NCL 38
#define NFL 12

// Scratch (alloc-free rule: __device__ globals)
__device__ float4 g_N0[N_TOTAL];   // {x, sin x, cos x, e^{-x}}
__device__ float4 g_N1[N_TOTAL];   // {e^{x}, a (x_i-role sum), b (x_j-role sum), 0}
__device__ float  g_wc[NCL];
__device__ float  g_wf[NFL];
__device__ int    g_e64;           // 1 if edge_index is int64, 0 if int32

__device__ __forceinline__ float safe_inv_f(float v) {
    float w = (fabsf(v) < 0.01f) ? ((v >= 0.0f) ? 0.01f : -0.01f) : v;
    return __fdividef(1.0f, w);
}

// ---------------- dtype probe: int64 vs int32 edge_index ----------------
__global__ void detect_kernel(const void* eidx_raw) {
    const long long* p = (const long long*)eidx_raw;
    int ok = 1;
    for (int k = 0; k < 64; k++) {
        long long v = p[k];
        if (v < 0 || v >= N_TOTAL) { ok = 0; break; }
    }
    g_e64 = ok;
}

// ---------------- setup: collapse [f,-f] weights ----------------
__global__ void setup_kernel(const float* __restrict__ c_mask,
                             const float* __restrict__ f_mask,
                             const float* __restrict__ wc2,
                             const float* __restrict__ wf2) {
    int k = threadIdx.x;
    if (k < NCL) g_wc[k] = c_mask[k] * (wc2[k] - wc2[k + NCL]);
    if (k < NFL) g_wf[k] = f_mask[k] * (wf2[k] - wf2[k + NFL]);
}

// ---------------- node pass: F(x) -> out, plus per-node tables ----------------
__global__ void node_kernel(const float* __restrict__ x, float* __restrict__ out) {
    int n = blockIdx.x * blockDim.x + threadIdx.x;
    if (n >= N_TOTAL) return;
    float xv = x[n];
    float s, c;
    __sincosf(xv, &s, &c);
    float E = __expf(-xv);
    float R = __expf(xv);
    float inv  = safe_inv_f(xv);
    float inv2 = inv * inv;
    float th = (R - E) * __fdividef(1.0f, R + E);     // tanh(x)
    float sg = __fdividef(1.0f, 1.0f + E);            // sigmoid(x)
    float rl = fmaxf(xv, 0.0f);
    float x2 = xv * xv;

    const float* wf = g_wf;
    float F = wf[0]
            + wf[1]*s + wf[2]*c + wf[3]*xv*s
            + wf[4]*xv + wf[5]*x2
            + wf[6]*inv + wf[7]*inv2 + wf[8]*inv2*inv
            + wf[9]*th + wf[10]*sg + wf[11]*rl;
    out[n] = F;   // F_COEF = 1; edge kernel accumulates on top

    const float* wc = g_wc;
    // node-as-x_i contribution (feature idx 0,3,6,10,18,19,26,27,28)
    float a = wc[0]*xv + wc[3]*x2 + wc[6]*inv + wc[10]*inv2
            + wc[18]*s + wc[19]*c + wc[26]*th + wc[27]*sg + wc[28]*rl;
    // node-as-x_j contribution (feature idx 1,4,7,11,20,21,29,30,31)
    float b = wc[1]*xv + wc[4]*x2 + wc[7]*inv + wc[11]*inv2
            + wc[20]*s + wc[21]*c + wc[29]*th + wc[30]*sg + wc[31]*rl;

    g_N0[n] = make_float4(xv, s, c, E);
    g_N1[n] = make_float4(R, a, b, 0.0f);
}

// ---------------- edge pass: coupled features + segment-sum atomics ----------------
__global__ void __launch_bounds__(256)
edge_kernel(const void* __restrict__ eidx_raw,
            const float* __restrict__ edge_attr,
            float* __restrict__ out) {
    // effective coupled weights (runtime values, cached in regs across both edges)
    const float wd1  = g_wc[2],  wd2  = g_wc[5];
    const float wid  = g_wc[8],  wis  = g_wc[9],  wid2 = g_wc[12], wis2 = g_wc[13];
    const float wsd  = g_wc[14], wcd  = g_wc[15], wss  = g_wc[16], wcs  = g_wc[17];
    const float wxx  = g_wc[22], wxsj = g_wc[23], wxsi = g_wc[24], wsdcs = g_wc[25];
    const float wthd = g_wc[32], wsgd = g_wc[33], wrld = g_wc[34];
    const float wths = g_wc[35], wsgs = g_wc[36], wrls = g_wc[37];

    long long e0 = (long long)(blockIdx.x * blockDim.x + threadIdx.x) * 2;
    if (e0 >= N_EDGES) return;

    // edge_index row 0 = src (x_j), row 1 = dst (x_i). Two edges per thread,
    // dtype-dispatched (uniform branch; g_e64 set by detect_kernel).
    int j0, j1, i0, i1;
    if (g_e64) {
        const long long* e = (const long long*)eidx_raw;
        longlong2 srcp = *reinterpret_cast<const longlong2*>(e + e0);
        longlong2 dstp = *reinterpret_cast<const longlong2*>(e + N_EDGES + e0);
        j0 = (int)srcp.x; j1 = (int)srcp.y;
        i0 = (int)dstp.x; i1 = (int)dstp.y;
    } else {
        const int* e = (const int*)eidx_raw;
        int2 srcp = *reinterpret_cast<const int2*>(e + e0);
        int2 dstp = *reinterpret_cast<const int2*>(e + N_EDGES + e0);
        j0 = srcp.x; j1 = srcp.y;
        i0 = dstp.x; i1 = dstp.y;
    }

#pragma unroll
    for (int k = 0; k < 2; k++) {
        int j = k ? j1 : j0;   // source  -> x_j
        int i = k ? i1 : i0;   // target  -> x_i, aggregation idx

        float4 n0i = __ldg(&g_N0[i]);
        float4 n0j = __ldg(&g_N0[j]);
        float4 n1i = __ldg(&g_N1[i]);
        float4 n1j = __ldg(&g_N1[j]);
        float xi = n0i.x, si = n0i.y, ci = n0i.z, Ei = n0i.w;
        float xj = n0j.x, sj = n0j.y, cj = n0j.z, Ej = n0j.w;
        float Ri = n1i.x, ai = n1i.y;
        float bj = n1j.z;

        float d  = xj - xi;
        float sm = xj + xi;

        // trig of d and s from per-node sin/cos (angle-sum identities)
        float p1 = sj * ci, p2 = cj * si, p3 = ci * cj, p4 = si * sj;
        float sind = p1 - p2, sins = p1 + p2;
        float cosd = p3 + p4, coss = p3 - p4;

        float invd = safe_inv_f(d);
        float invs = safe_inv_f(sm);

        // activations of d and s from precomputed exponentials
        float vd  = Ej * Ri;             // e^{-d}
        float vs  = Ei * Ej;             // e^{-s}
        float vd2 = vd * vd, vs2 = vs * vs;
        float thd = (1.0f - vd2) * __fdividef(1.0f, 1.0f + vd2);
        float sgd = __fdividef(1.0f, 1.0f + vd);
        float ths = (1.0f - vs2) * __fdividef(1.0f, 1.0f + vs2);
        float sgs = __fdividef(1.0f, 1.0f + vs);

        float core = ai + bj;
        core = fmaf(wd1,  d,            core);
        core = fmaf(wd2,  d * d,        core);
        core = fmaf(wid,  invd,         core);
        core = fmaf(wid2, invd * invd,  core);
        core = fmaf(wis,  invs,         core);
        core = fmaf(wis2, invs * invs,  core);
        core = fmaf(wsd,  sind,         core);
        core = fmaf(wcd,  cosd,         core);
        core = fmaf(wss,  sins,         core);
        core = fmaf(wcs,  coss,         core);
        core = fmaf(wxx,  xi * xj,      core);
        core = fmaf(wxsj, xi * sj,      core);
        core = fmaf(wxsi, xj * si,      core);
        core = fmaf(wsdcs, sind * coss, core);
        core = fmaf(wthd, thd,          core);
        core = fmaf(wsgd, sgd,          core);
        core = fmaf(wrld, fmaxf(d, 0.0f),  core);
        core = fmaf(wths, ths,          core);
        core = fmaf(wsgs, sgs,          core);
        core = fmaf(wrls, fmaxf(sm, 0.0f), core);

        // edge_attr_all[src % 100, dst % 100]
        int ri   = j % NUM_ATOMS;
        int cidx = i % NUM_ATOMS;
        float ea = __ldg(&edge_attr[ri * NUM_ATOMS + cidx]);

        atomicAdd(&out[i], ea * core);   // segment_sum over dst
    }
}

extern "C" void kernel_launch(void* const* d_in, const int* in_sizes, int n_in,
                              void* d_out, int out_size) {
    // Identify inputs by element count (robust to whether scalar `t` occupies
    // a slot). Expected (reference order): t?, x[10000], edge_index[2000000],
    // c_mask[38], f_mask[12], wc_2[76], wf_2[24], edge_attr_all[10000].
    const float* x   = nullptr;
    const void*  ei  = nullptr;
    const float* cm  = nullptr;
    const float* fm  = nullptr;
    const float* wc2 = nullptr;
    const float* wf2 = nullptr;
    const float* ea  = nullptr;
    for (int idx = 0; idx < n_in; idx++) {
        int s = in_sizes[idx];
        if (s == 2 * N_EDGES)      ei  = d_in[idx];
        else if (s == NCL)         cm  = (const float*)d_in[idx];
        else if (s == NFL)         fm  = (const float*)d_in[idx];
        else if (s == 2 * NCL)     wc2 = (const float*)d_in[idx];
        else if (s == 2 * NFL)     wf2 = (const float*)d_in[idx];
        else if (s == N_TOTAL) {
            if (!x) x = (const float*)d_in[idx];   // x comes first
            else    ea = (const float*)d_in[idx];  // edge_attr_all second
        }
    }
    float* out = (float*)d_out;

    detect_kernel<<<1, 1>>>(ei);
    setup_kernel<<<1, 64>>>(cm, fm, wc2, wf2);
    node_kernel<<<(N_TOTAL + 255) / 256, 256>>>(x, out);
    int threads = N_EDGES / 2;                    // 2 edges per thread
    edge_kernel<<<(threads + 255) / 256, 256>>>(ei, ea, out);
}

// round 3
// speedup vs baseline: 1.3155x; 1.3155x over previous
#include <cuda_runtime.h>
#include <cuda_fp16.h>

// Problem constants (fixed by the dataset)
#define N_TOTAL   10000
#define NUM_ATOMS 100
#define N_EDGES   1000000
#define NCL 38
#define NFL 12
#define EPT 4              // edges per thread in edge kernel

// Scratch (alloc-free rule: __device__ globals)
__device__ float4 g_NA[N_TOTAL];   // {x, a(i-role), b(j-role), half2(sin,cos)}
__device__ float  g_wc[NCL];
__device__ float  g_wf[NFL];
__device__ int    g_e64;           // 1 if edge_index is int64, 0 if int32

__device__ __forceinline__ float safe_inv_f(float v) {
    float w = (fabsf(v) < 0.01f) ? ((v >= 0.0f) ? 0.01f : -0.01f) : v;
    return __fdividef(1.0f, w);
}

// ---------------- fused setup: weights collapse + dtype probe ----------------
__global__ void setup_kernel(const float* __restrict__ c_mask,
                             const float* __restrict__ f_mask,
                             const float* __restrict__ wc2,
                             const float* __restrict__ wf2,
                             const void* eidx_raw) {
    int k = threadIdx.x;
    if (k < NCL) g_wc[k] = c_mask[k] * (wc2[k] - wc2[k + NCL]);
    if (k < NFL) g_wf[k] = f_mask[k] * (wf2[k] - wf2[k + NFL]);
    if (k == 0) {
        const long long* p = (const long long*)eidx_raw;
        int ok = 1;
        for (int q = 0; q < 64; q++) {
            long long v = p[q];
            if (v < 0 || v >= N_TOTAL) { ok = 0; break; }
        }
        g_e64 = ok;
    }
}

// ---------------- node pass: F(x) -> out, plus packed per-node table ----------------
__global__ void node_kernel(const float* __restrict__ x, float* __restrict__ out) {
    int n = blockIdx.x * blockDim.x + threadIdx.x;
    if (n >= N_TOTAL) return;
    float xv = x[n];
    float s, c;
    __sincosf(xv, &s, &c);
    float E = __expf(-xv);
    float R = __expf(xv);
    float inv  = safe_inv_f(xv);
    float inv2 = inv * inv;
    float th = (R - E) * __fdividef(1.0f, R + E);     // tanh(x)
    float sg = __fdividef(1.0f, 1.0f + E);            // sigmoid(x)
    float rl = fmaxf(xv, 0.0f);
    float x2 = xv * xv;

    const float* wf = g_wf;
    float F = wf[0]
            + wf[1]*s + wf[2]*c + wf[3]*xv*s
            + wf[4]*xv + wf[5]*x2
            + wf[6]*inv + wf[7]*inv2 + wf[8]*inv2*inv
            + wf[9]*th + wf[10]*sg + wf[11]*rl;
    out[n] = F;   // F_COEF = 1; edge kernel accumulates on top

    const float* wc = g_wc;
    // node-as-x_i contribution (feature idx 0,3,6,10,18,19,26,27,28)
    float a = wc[0]*xv + wc[3]*x2 + wc[6]*inv + wc[10]*inv2
            + wc[18]*s + wc[19]*c + wc[26]*th + wc[27]*sg + wc[28]*rl;
    // node-as-x_j contribution (feature idx 1,4,7,11,20,21,29,30,31)
    float b = wc[1]*xv + wc[4]*x2 + wc[7]*inv + wc[11]*inv2
            + wc[20]*s + wc[21]*c + wc[29]*th + wc[30]*sg + wc[31]*rl;

    __half2 sc = __floats2half2_rn(s, c);
    g_NA[n] = make_float4(xv, a, b, __uint_as_float(*reinterpret_cast<unsigned*>(&sc)));
}

// ---------------- edge pass: coupled features + segment-sum atomics ----------------
__global__ void __launch_bounds__(256)
edge_kernel(const void* __restrict__ eidx_raw,
            const float* __restrict__ edge_attr,
            float* __restrict__ out) {
    // effective coupled weights (runtime values, kept in regs across all edges)
    const float wd1  = g_wc[2],  wd2  = g_wc[5];
    const float wid  = g_wc[8],  wis  = g_wc[9],  wid2 = g_wc[12], wis2 = g_wc[13];
    const float wsd  = g_wc[14], wcd  = g_wc[15], wss  = g_wc[16], wcs  = g_wc[17];
    const float wxx  = g_wc[22], wxsj = g_wc[23], wxsi = g_wc[24], wsdcs = g_wc[25];
    const float wthd = g_wc[32], wsgd = g_wc[33], wrld = g_wc[34];
    const float wths = g_wc[35], wsgs = g_wc[36], wrls = g_wc[37];

    int tid = blockIdx.x * blockDim.x + threadIdx.x;
    int e0 = tid * EPT;
    if (e0 >= N_EDGES) return;

    // ---- load 4 edge index pairs (dtype-dispatched, uniform branch) ----
    int js[EPT], is[EPT];
    if (g_e64) {
        const long long* e = (const long long*)eidx_raw;
        longlong2 s0 = *reinterpret_cast<const longlong2*>(e + e0);
        longlong2 s1 = *reinterpret_cast<const longlong2*>(e + e0 + 2);
        longlong2 d0 = *reinterpret_cast<const longlong2*>(e + N_EDGES + e0);
        longlong2 d1 = *reinterpret_cast<const longlong2*>(e + N_EDGES + e0 + 2);
        js[0] = (int)s0.x; js[1] = (int)s0.y; js[2] = (int)s1.x; js[3] = (int)s1.y;
        is[0] = (int)d0.x; is[1] = (int)d0.y; is[2] = (int)d1.x; is[3] = (int)d1.y;
    } else {
        const int* e = (const int*)eidx_raw;
        int4 sp = *reinterpret_cast<const int4*>(e + e0);
        int4 dp = *reinterpret_cast<const int4*>(e + N_EDGES + e0);
        js[0] = sp.x; js[1] = sp.y; js[2] = sp.z; js[3] = sp.w;
        is[0] = dp.x; is[1] = dp.y; is[2] = dp.z; is[3] = dp.w;
    }

    // ---- issue all gathers up front (max MLP) ----
    float4 Nj[EPT], Ni[EPT];
    float  ea[EPT];
#pragma unroll
    for (int k = 0; k < EPT; k++) {
        Nj[k] = __ldg(&g_NA[js[k]]);
        Ni[k] = __ldg(&g_NA[is[k]]);
    }
#pragma unroll
    for (int k = 0; k < EPT; k++) {
        int ri   = js[k] % NUM_ATOMS;
        int cidx = is[k] % NUM_ATOMS;
        ea[k] = __ldg(&edge_attr[ri * NUM_ATOMS + cidx]);
    }

#pragma unroll
    for (int k = 0; k < EPT; k++) {
        float xi = Ni[k].x, ai = Ni[k].y;
        float xj = Nj[k].x, bj = Nj[k].z;
        unsigned ui = __float_as_uint(Ni[k].w);
        unsigned uj = __float_as_uint(Nj[k].w);
        float2 sci = __half22float2(*reinterpret_cast<__half2*>(&ui));
        float2 scj = __half22float2(*reinterpret_cast<__half2*>(&uj));
        float si = sci.x, ci = sci.y;
        float sj = scj.x, cj = scj.y;

        float d  = xj - xi;
        float sm = xj + xi;

        // trig of d and s from per-node sin/cos (angle-sum identities)
        float p1 = sj * ci, p2 = cj * si, p3 = ci * cj, p4 = si * sj;
        float sind = p1 - p2, sins = p1 + p2;
        float cosd = p3 + p4, coss = p3 - p4;

        float invd = safe_inv_f(d);
        float invs = safe_inv_f(sm);

        // activations of d and s via per-edge exp (MUFU is cheap)
        float vd  = __expf(-d);          // e^{-d}
        float vs  = __expf(-sm);         // e^{-s}
        float vd2 = vd * vd, vs2 = vs * vs;
        float thd = (1.0f - vd2) * __fdividef(1.0f, 1.0f + vd2);
        float sgd = __fdividef(1.0f, 1.0f + vd);
        float ths = (1.0f - vs2) * __fdividef(1.0f, 1.0f + vs2);
        float sgs = __fdividef(1.0f, 1.0f + vs);

        float core = ai + bj;
        core = fmaf(wd1,  d,            core);
        core = fmaf(wd2,  d * d,        core);
        core = fmaf(wid,  invd,         core);
        core = fmaf(wid2, invd * invd,  core);
        core = fmaf(wis,  invs,         core);
        core = fmaf(wis2, invs * invs,  core);
        core = fmaf(wsd,  sind,         core);
        core = fmaf(wcd,  cosd,         core);
        core = fmaf(wss,  sins,         core);
        core = fmaf(wcs,  coss,         core);
        core = fmaf(wxx,  xi * xj,      core);
        core = fmaf(wxsj, xi * sj,      core);
        core = fmaf(wxsi, xj * si,      core);
        core = fmaf(wsdcs, sind * coss, core);
        core = fmaf(wthd, thd,          core);
        core = fmaf(wsgd, sgd,          core);
        core = fmaf(wrld, fmaxf(d, 0.0f),  core);
        core = fmaf(wths, ths,          core);
        core = fmaf(wsgs, sgs,          core);
        core = fmaf(wrls, fmaxf(sm, 0.0f), core);

        atomicAdd(&out[is[k]], ea[k] * core);   // segment_sum over dst
    }
}

extern "C" void kernel_launch(void* const* d_in, const int* in_sizes, int n_in,
                              void* d_out, int out_size) {
    // Identify inputs by element count (robust to whether scalar `t` occupies
    // a slot). Reference order: t?, x[10000], edge_index[2000000], c_mask[38],
    // f_mask[12], wc_2[76], wf_2[24], edge_attr_all[10000].
    const float* x   = nullptr;
    const void*  ei  = nullptr;
    const float* cm  = nullptr;
    const float* fm  = nullptr;
    const float* wc2 = nullptr;
    const float* wf2 = nullptr;
    const float* ea  = nullptr;
    for (int idx = 0; idx < n_in; idx++) {
        int s = in_sizes[idx];
        if (s == 2 * N_EDGES)      ei  = d_in[idx];
        else if (s == NCL)         cm  = (const float*)d_in[idx];
        else if (s == NFL)         fm  = (const float*)d_in[idx];
        else if (s == 2 * NCL)     wc2 = (const float*)d_in[idx];
        else if (s == 2 * NFL)     wf2 = (const float*)d_in[idx];
        else if (s == N_TOTAL) {
            if (!x) x = (const float*)d_in[idx];   // x comes first
            else    ea = (const float*)d_in[idx];  // edge_attr_all second
        }
    }
    float* out = (float*)d_out;

    setup_kernel<<<1, 64>>>(cm, fm, wc2, wf2, ei);
    node_kernel<<<(N_TOTAL + 255) / 256, 256>>>(x, out);
    int threads = N_EDGES / EPT;
    edge_kernel<<<(threads + 255) / 256, 256>>>(ei, ea, out);
}